// round 16
// baseline (speedup 1.0000x reference)
#include <cuda_runtime.h>
#include <cuda_bf16.h>
#include <cuda_fp16.h>
#include <cstdint>

#define NN 100000
#define NE 3200000
#define IN_DIM 512
#define HID 64
#define OUTD 5

// ---------------------------------------------------------------------------
// Device scratch
// ---------------------------------------------------------------------------
__device__ __align__(16) float g_deg[NN];
__device__ __align__(16) int   g_cnt[NN];
__device__ __align__(16) int   g_rowptr[NN + 1];
__device__ __align__(16) int   g_wofs[NN];
__device__ __align__(16) float g_dinv[NN];
__device__ __align__(16) int2  g_em[NE];                 // {src, norm bits}
__device__ __align__(16) __half g_h16[(size_t)NN * HID]; // GEMM out (fp16)
__device__ __align__(16) __half g_ha[(size_t)NN * HID];  // agg1 out (fp16)
__device__ __align__(16) __half g_w1t[64 * IN_DIM];      // W1^T fp16 [n][K]
__device__ __align__(16) __half g_w2t[64 * HID];         // W2^T fp16 [n][K]
__device__ __align__(16) int   g_bsum[128];
__device__ int g_odd_nonzero;

// ---------------------------------------------------------------------------
// Preprocessing
// ---------------------------------------------------------------------------
__global__ void zero_kernel() {
    int i = blockIdx.x * blockDim.x + threadIdx.x;
    if (i == 0) g_odd_nonzero = 0;
    if (i < NN) { g_deg[i] = 0.0f; g_cnt[i] = 0; }
}

__global__ void detect_dtype_kernel(const int* __restrict__ ei32) {
    int tid = blockIdx.x * blockDim.x + threadIdx.x;
    int idx = 2 * (tid * 195 + 1) + 1;
    if (idx < NE && ei32[idx] != 0) atomicExch(&g_odd_nonzero, 1);
}

__global__ void deg_kernel(const void* __restrict__ ei, const float* __restrict__ ew) {
    int e = blockIdx.x * blockDim.x + threadIdx.x;
    if (e >= NE) return;
    int dst;
    if (g_odd_nonzero) dst = ((const int*)ei)[NE + e];
    else               dst = (int)((const long long*)ei)[NE + e];
    atomicAdd(&g_deg[dst], ew[e]);
    atomicAdd(&g_cnt[dst], 1);
}

__global__ void scan1_kernel() {
    __shared__ int s[1024];
    int tid = threadIdx.x;
    int i = blockIdx.x * 1024 + tid;
    int v = (i < NN) ? g_cnt[i] : 0;
    s[tid] = v;
    __syncthreads();
    #pragma unroll
    for (int off = 1; off < 1024; off <<= 1) {
        int t = (tid >= off) ? s[tid - off] : 0;
        __syncthreads();
        s[tid] += t;
        __syncthreads();
    }
    if (i < NN) g_rowptr[i] = s[tid] - v;
    if (tid == 1023) g_bsum[blockIdx.x] = s[1023];
}

__global__ void scan2_kernel() {
    int tid = threadIdx.x;                 // 128 threads
    int nb = (NN + 1023) / 1024;           // 98
    int v = (tid < nb) ? g_bsum[tid] : 0;
    int lane = tid & 31, w = tid >> 5;
    int x = v;
    #pragma unroll
    for (int o = 1; o < 32; o <<= 1) {
        int y = __shfl_up_sync(0xFFFFFFFFu, x, o);
        if (lane >= o) x += y;
    }
    __shared__ int ws[4];
    if (lane == 31) ws[w] = x;
    __syncthreads();
    int add = 0;
    for (int j = 0; j < w; j++) add += ws[j];
    x += add;
    if (tid < nb) g_bsum[tid] = x - v;
    if (tid == nb - 1) g_rowptr[NN] = x;
}

__global__ void scan3_kernel() {
    int i = blockIdx.x * blockDim.x + threadIdx.x;
    if (i < NN) {
        int v = g_rowptr[i] + g_bsum[i >> 10];
        g_rowptr[i] = v;
        g_wofs[i]   = v;
        g_dinv[i]   = rsqrtf(g_deg[i] + 1.0f);
    }
}

__global__ void fill_kernel(const void* __restrict__ ei, const float* __restrict__ ew) {
    int e = blockIdx.x * blockDim.x + threadIdx.x;
    if (e >= NE) return;
    int src, dst;
    if (g_odd_nonzero) {
        const int* p = (const int*)ei;
        src = p[e]; dst = p[NE + e];
    } else {
        const long long* p = (const long long*)ei;
        src = (int)p[e]; dst = (int)p[NE + e];
    }
    float w = g_dinv[src] * ew[e] * g_dinv[dst];
    int pos = atomicAdd(&g_wofs[dst], 1);
    g_em[pos] = make_int2(src, __float_as_int(w));
}

// ---------------------------------------------------------------------------
// Both W transposes in one launch. z=0 -> W1 (K=IN_DIM), z=1 -> W2 (K=HID).
// ---------------------------------------------------------------------------
__global__ void transpose_both(const float* __restrict__ W1, __half* __restrict__ o1,
                               const float* __restrict__ W2, __half* __restrict__ o2) {
    const float* W = blockIdx.z ? W2 : W1;
    __half* out    = blockIdx.z ? o2 : o1;
    int K          = blockIdx.z ? HID : IN_DIM;
    if ((int)blockIdx.x * 32 >= K) return;

    __shared__ float t[32][33];
    int k0 = blockIdx.x * 32, n0 = blockIdx.y * 32;
    int tx = threadIdx.x, ty = threadIdx.y;
    for (int i = ty; i < 32; i += 8)
        t[i][tx] = W[(size_t)(k0 + i) * 64 + n0 + tx];
    __syncthreads();
    for (int i = ty; i < 32; i += 8)
        out[(size_t)(n0 + i) * K + k0 + tx] = __float2half_rn(t[tx][i]);
}

// ---------------------------------------------------------------------------
// fp16 tensor-core GEMM. C16[M,64] = A[M,K] @ Bt^T, Bt = [64][K] fp16.
// A: register-double-buffered streaming (+fp32->fp16 convert for layer 1).
// B: cp.async double-buffered (no register staging, no STS pass).
// Fragments: ldmatrix.x4 (A) + paired-nt ldmatrix.x4 (B).
// ---------------------------------------------------------------------------
#define GP 72
#define SM_AH 0
#define SM_B  (128 * GP)
#define SM_ELEMS (128 * GP + 2 * 64 * GP)   // 18432 halves = 36864 B

__device__ __forceinline__ uint32_t smemu32(const void* p) {
    return (uint32_t)__cvta_generic_to_shared(p);
}
#define CP_ASYNC16(dst, src) \
    asm volatile("cp.async.cg.shared.global [%0], [%1], 16;" :: "r"(dst), "l"(src))
#define CP_COMMIT() asm volatile("cp.async.commit_group;" ::: "memory")
#define CP_WAIT0()  asm volatile("cp.async.wait_group 0;" ::: "memory")

__device__ __forceinline__ void mma_fp16(float* c, const uint32_t* a, uint32_t b0, uint32_t b1) {
    asm volatile(
        "mma.sync.aligned.m16n8k16.row.col.f32.f16.f16.f32 "
        "{%0,%1,%2,%3}, {%4,%5,%6,%7}, {%8,%9}, {%0,%1,%2,%3};"
        : "+f"(c[0]), "+f"(c[1]), "+f"(c[2]), "+f"(c[3])
        : "r"(a[0]), "r"(a[1]), "r"(a[2]), "r"(a[3]), "r"(b0), "r"(b1));
}
__device__ __forceinline__ void ldsm_x4(uint32_t* r, uint32_t addr) {
    asm volatile("ldmatrix.sync.aligned.m8n8.x4.shared.b16 {%0,%1,%2,%3}, [%4];"
        : "=r"(r[0]), "=r"(r[1]), "=r"(r[2]), "=r"(r[3]) : "r"(addr));
}

template <typename TA>
__global__ void __launch_bounds__(256)
gemm_mma(const TA* __restrict__ A, const __half* __restrict__ Bt,
         __half* __restrict__ C, int M, int K) {
    extern __shared__ __half sm[];
    __half* Ah = sm + SM_AH;
    __half* Bs = sm + SM_B;      // two 64*GP buffers

    int tid = threadIdx.x;
    int wid = tid >> 5;
    int lane = tid & 31;
    int r0 = lane >> 2;
    int tg = lane & 3;
    int row0 = blockIdx.x * 128;

    float acc[8][4];
    #pragma unroll
    for (int nt = 0; nt < 8; nt++)
        #pragma unroll
        for (int j = 0; j < 4; j++) acc[nt][j] = 0.f;

    float4 pa[8];    // fp32 A path
    uint4  ph[4];    // fp16 A path

    auto prefetchA = [&](int c0) {
        if constexpr (sizeof(TA) == 4) {
            #pragma unroll
            for (int s = 0; s < 8; s++) {
                int idx = tid + s * 256;
                int r = idx >> 4;
                int col = (idx & 15) * 4;
                int gr = row0 + r;
                if (gr >= M) gr = M - 1;
                pa[s] = *(const float4*)((const float*)A + (size_t)gr * K + c0 + col);
            }
        } else {
            #pragma unroll
            for (int s = 0; s < 4; s++) {
                int idx = tid + s * 256;
                int r = idx >> 3;
                int q = idx & 7;
                int gr = row0 + r;
                if (gr >= M) gr = M - 1;
                ph[s] = *(const uint4*)((const __half*)A + (size_t)gr * K + c0 + q * 8);
            }
        }
    };
    auto issueB = [&](int c0, int buf) {
        __half* Bb = Bs + buf * (64 * GP);
        #pragma unroll
        for (int s = 0; s < 2; s++) {
            int u = tid + s * 256;
            int n = u >> 3;
            int q = u & 7;
            CP_ASYNC16(smemu32(Bb + n * GP + q * 8), Bt + (size_t)n * K + c0 + q * 8);
        }
        CP_COMMIT();
    };

    issueB(0, 0);
    prefetchA(0);

    // ldmatrix lane addressing (constant parts)
    int a_row = lane & 15;
    int a_kof = (lane >> 4) << 3;
    uint32_t a_base = smemu32(Ah + (wid * 16 + a_row) * GP + a_kof);
    int b_m  = lane >> 4;              // matrix-pair selector (nt, nt+1)
    int b_r  = lane & 7;
    int b_kof = ((lane >> 3) & 1) << 3;

    int nch = K >> 6;
    for (int c = 0; c < nch; c++) {
        __syncthreads();               // prior chunk's Ah readers done
        // stage A (convert if fp32)
        if constexpr (sizeof(TA) == 4) {
            #pragma unroll
            for (int s = 0; s < 8; s++) {
                int idx = tid + s * 256;
                int r = idx >> 4;
                int col = (idx & 15) * 4;
                *(__half2*)(Ah + r * GP + col)     = __floats2half2_rn(pa[s].x, pa[s].y);
                *(__half2*)(Ah + r * GP + col + 2) = __floats2half2_rn(pa[s].z, pa[s].w);
            }
        } else {
            #pragma unroll
            for (int s = 0; s < 4; s++) {
                int idx = tid + s * 256;
                int r = idx >> 3;
                int q = idx & 7;
                *(uint4*)(Ah + r * GP + q * 8) = ph[s];
            }
        }
        CP_WAIT0();                    // B buffer (c&1) arrived
        __syncthreads();

        if (c + 1 < nch) {
            prefetchA((c + 1) << 6);
            issueB((c + 1) << 6, (c + 1) & 1);
        }

        uint32_t b_base = smemu32(Bs + (c & 1) * (64 * GP) + (b_m * 8 + b_r) * GP + b_kof);

        #pragma unroll
        for (int ks = 0; ks < 64; ks += 16) {
            uint32_t ah[4];
            ldsm_x4(ah, a_base + ks * 2);
            #pragma unroll
            for (int p = 0; p < 4; p++) {
                uint32_t bb[4];
                ldsm_x4(bb, b_base + (p * 16 * GP + ks) * 2);
                mma_fp16(acc[2 * p],     ah, bb[0], bb[1]);
                mma_fp16(acc[2 * p + 1], ah, bb[2], bb[3]);
            }
        }
    }

    int rowa = row0 + wid * 16 + r0;
    int rowb = rowa + 8;
    #pragma unroll
    for (int nt = 0; nt < 8; nt++) {
        int col = nt * 8 + tg * 2;
        if (rowa < M)
            *(__half2*)(C + (size_t)rowa * 64 + col) = __floats2half2_rn(acc[nt][0], acc[nt][1]);
        if (rowb < M)
            *(__half2*)(C + (size_t)rowb * 64 + col) = __floats2half2_rn(acc[nt][2], acc[nt][3]);
    }
}

// ---------------------------------------------------------------------------
// Aggregation core (8-deep fp16 gather pipeline) + bias + relu
// ---------------------------------------------------------------------------
__device__ __forceinline__ void hacc(float* a, float w, uint4 v) {
    float2 f0 = __half22float2(*(__half2*)&v.x);
    float2 f1 = __half22float2(*(__half2*)&v.y);
    float2 f2 = __half22float2(*(__half2*)&v.z);
    float2 f3 = __half22float2(*(__half2*)&v.w);
    a[0] = fmaf(w, f0.x, a[0]); a[1] = fmaf(w, f0.y, a[1]);
    a[2] = fmaf(w, f1.x, a[2]); a[3] = fmaf(w, f1.y, a[3]);
    a[4] = fmaf(w, f2.x, a[4]); a[5] = fmaf(w, f2.y, a[5]);
    a[6] = fmaf(w, f3.x, a[6]); a[7] = fmaf(w, f3.y, a[7]);
}

__device__ __forceinline__ void agg_core(
    const __half* __restrict__ h16, const float* __restrict__ bias,
    int node, int sub, float* r)
{
    int beg = g_rowptr[node];
    int end = g_rowptr[node + 1];
    const uint4* hp = (const uint4*)h16;
    float a[8];
    #pragma unroll
    for (int j = 0; j < 8; j++) a[j] = 0.f;

    int e = beg;
    for (; e + 8 <= end; e += 8) {
        int2 m[8];
        #pragma unroll
        for (int j = 0; j < 8; j++) m[j] = g_em[e + j];
        uint4 v[8];
        #pragma unroll
        for (int j = 0; j < 8; j++) v[j] = hp[m[j].x * 8 + sub];
        #pragma unroll
        for (int j = 0; j < 8; j++) hacc(a, __int_as_float(m[j].y), v[j]);
    }
    for (; e + 4 <= end; e += 4) {
        int2 m0 = g_em[e], m1 = g_em[e + 1], m2 = g_em[e + 2], m3 = g_em[e + 3];
        uint4 v0 = hp[m0.x * 8 + sub];
        uint4 v1 = hp[m1.x * 8 + sub];
        uint4 v2 = hp[m2.x * 8 + sub];
        uint4 v3 = hp[m3.x * 8 + sub];
        hacc(a, __int_as_float(m0.y), v0);
        hacc(a, __int_as_float(m1.y), v1);
        hacc(a, __int_as_float(m2.y), v2);
        hacc(a, __int_as_float(m3.y), v3);
    }
    for (; e < end; e++) {
        int2 m = g_em[e];
        hacc(a, __int_as_float(m.y), hp[m.x * 8 + sub]);
    }

    float di = g_dinv[node];
    hacc(a, di * di, hp[node * 8 + sub]);

    const float4* b4 = (const float4*)bias;
    float4 bv0 = b4[sub * 2], bv1 = b4[sub * 2 + 1];
    r[0] = fmaxf(a[0] + bv0.x, 0.f); r[1] = fmaxf(a[1] + bv0.y, 0.f);
    r[2] = fmaxf(a[2] + bv0.z, 0.f); r[3] = fmaxf(a[3] + bv0.w, 0.f);
    r[4] = fmaxf(a[4] + bv1.x, 0.f); r[5] = fmaxf(a[5] + bv1.y, 0.f);
    r[6] = fmaxf(a[6] + bv1.z, 0.f); r[7] = fmaxf(a[7] + bv1.w, 0.f);
}

// Layer-1 aggregation: fp16 output (gemm2 rounds its A to fp16 anyway).
__global__ void __launch_bounds__(256)
aggregate1_k(const __half* __restrict__ h16, const float* __restrict__ bias,
             __half* __restrict__ outp) {
    int tid = threadIdx.x;
    int sub = tid & 7;
    int node = blockIdx.x * 32 + (tid >> 3);
    if (node >= NN) return;
    float r[8];
    agg_core(h16, bias, node, sub, r);
    uint4 o;
    *(__half2*)&o.x = __floats2half2_rn(r[0], r[1]);
    *(__half2*)&o.y = __floats2half2_rn(r[2], r[3]);
    *(__half2*)&o.z = __floats2half2_rn(r[4], r[5]);
    *(__half2*)&o.w = __floats2half2_rn(r[6], r[7]);
    ((uint4*)outp)[node * 8 + sub] = o;
}

// Layer-2 aggregation FUSED with the final 64->5 linear layer.
__global__ void __launch_bounds__(256)
aggregate2_final_k(const __half* __restrict__ h16, const float* __restrict__ bias,
                   const float* __restrict__ Wf, const float* __restrict__ bf,
                   float* __restrict__ outp) {
    __shared__ float Wfs[HID * OUTD];
    __shared__ float bfs[OUTD];
    int tid = threadIdx.x;
    for (int i = tid; i < HID * OUTD; i += 256) Wfs[i] = Wf[i];
    if (tid < OUTD) bfs[tid] = bf[tid];
    __syncthreads();

    int sub = tid & 7;
    int node = blockIdx.x * 32 + (tid >> 3);
    bool valid = node < NN;
    int node_c = valid ? node : NN - 1;

    float r[8];
    agg_core(h16, bias, node_c, sub, r);

    float p[OUTD];
    #pragma unroll
    for (int o = 0; o < OUTD; o++) p[o] = 0.f;
    #pragma unroll
    for (int j = 0; j < 8; j++) {
        int k = sub * 8 + j;
        #pragma unroll
        for (int o = 0; o < OUTD; o++)
            p[o] = fmaf(r[j], Wfs[k * OUTD + o], p[o]);
    }
    #pragma unroll
    for (int o = 0; o < OUTD; o++) {
        p[o] += __shfl_xor_sync(0xFFFFFFFFu, p[o], 1);
        p[o] += __shfl_xor_sync(0xFFFFFFFFu, p[o], 2);
        p[o] += __shfl_xor_sync(0xFFFFFFFFu, p[o], 4);
    }
    if (valid && sub == 0) {
        #pragma unroll
        for (int o = 0; o < OUTD; o++)
            outp[(size_t)node * OUTD + o] = p[o] + bfs[o];
    }
}

// ---------------------------------------------------------------------------
// Launch — gemm1 kept at slot #4 (profiled launch)
// ---------------------------------------------------------------------------
extern "C" void kernel_launch(void* const* d_in, const int* in_sizes, int n_in,
                              void* d_out, int out_size) {
    const float* x  = (const float*)d_in[0];
    const void*  ei = d_in[1];
    const float* ew = (const float*)d_in[2];
    const float* W1 = (const float*)d_in[3];
    const float* b1 = (const float*)d_in[4];
    const float* W2 = (const float*)d_in[5];
    const float* b2 = (const float*)d_in[6];
    const float* Wf = (const float*)d_in[7];
    const float* bf = (const float*)d_in[8];
    float* out = (float*)d_out;

    __half* h16 = nullptr;
    __half* ha  = nullptr;
    __half* w1t = nullptr;
    __half* w2t = nullptr;
    cudaGetSymbolAddress((void**)&h16, g_h16);
    cudaGetSymbolAddress((void**)&ha,  g_ha);
    cudaGetSymbolAddress((void**)&w1t, g_w1t);
    cudaGetSymbolAddress((void**)&w2t, g_w2t);

    const int SMEM_BYTES = SM_ELEMS * 2;   // 36864 < 48KB default

    const int TB = 256;
    int gN = (NN + TB - 1) / TB;
    int gE = (NE + TB - 1) / TB;
    int gG = (NN + 127) / 128;
    int gA = (NN + 31) / 32;               // 3125, exact
    int gS = (NN + 1023) / 1024;

    zero_kernel<<<gN, TB>>>();                                            // 1
    transpose_both<<<dim3(IN_DIM / 32, 2, 2), dim3(32, 8)>>>(W1, w1t, W2, w2t); // 2
    detect_dtype_kernel<<<32, 256>>>((const int*)ei);                     // 3
    gemm_mma<float><<<gG, TB, SMEM_BYTES>>>(x, w1t, h16, NN, IN_DIM);     // 4 <- profiled
    deg_kernel<<<gE, TB>>>(ei, ew);                                       // 5
    scan1_kernel<<<gS, 1024>>>();                                         // 6
    scan2_kernel<<<1, 128>>>();                                           // 7
    scan3_kernel<<<gN, TB>>>();                                           // 8
    fill_kernel<<<gE, TB>>>(ei, ew);                                      // 9

    aggregate1_k<<<gA, TB>>>(h16, b1, ha);                                // 10
    gemm_mma<__half><<<gG, TB, SMEM_BYTES>>>(ha, w2t, h16, NN, HID);      // 11
    aggregate2_final_k<<<gA, TB>>>(h16, b2, Wf, bf, out);                 // 12
}